// round 11
// baseline (speedup 1.0000x reference)
#include <cuda_runtime.h>
#include <cuda_bf16.h>

// GroupTokenizer: y[B,T,C] fp32, left/right edges [C,K] fp32.
// Output buffer (fp32): [ labels(B*T*C) | reg(B*T*C*K) ].
// B=32, T=4096, C=8, K=64.
//
// TERMINAL FORM — DRAM-write-roofline bound. Best/stable: 45.536 us
// (x4 exact repeats over 6 runs, rel_err 0.0), ~6.1 TB/s sustained on
// 4 MB read + 272 MB write.
//
// Measured-neutral: store width 128b/256b, cache-op default/.cs,
// smem vs shuffle exchange, label packing, wave count 1..7,
// occupancy 60%..86%. Measured-regressive: persistent multi-tile
// (occupancy < ~56%). Model-excluded: TMA store epilogue (path-
// independent cap; LTS below DRAM%), HBM channel striding, any
// compute-side change (issue 19%, fma 3%).

#define KBINS 64
#define CCH 8
#define ESTR 65            // padded shared stride to avoid bank conflicts
#define TPB 512            // threads per block == elements per block
#define EPSW 1e-12f

__global__ void __launch_bounds__(TPB)
gt_kernel(const float* __restrict__ y,
          const float* __restrict__ le,
          const float* __restrict__ re,
          float* __restrict__ out_labels,
          float* __restrict__ out_reg)
{
    __shared__ float s_l[CCH * ESTR];
    __shared__ float s_r[CCH * ESTR];

    const int tid = threadIdx.x;

    // Load edge tables into shared (padded stride). Only barrier in kernel.
    for (int i = tid; i < CCH * KBINS; i += TPB) {
        int c = i >> 6;          // i / KBINS
        int k = i & (KBINS - 1); // i % KBINS
        s_l[c * ESTR + k] = le[i];
        s_r[c * ESTR + k] = re[i];
    }
    __syncthreads();

    const int base = blockIdx.x * TPB;
    const int idx  = base + tid;     // flattened (b,t,c); grid sized exactly

    // ---------------- Phase 1: label + delta per element ----------------
    const float yv = y[idx];
    const int   c  = idx & (CCH - 1);          // channel = fastest dim
    const float* lrow = s_l + c * ESTR;
    const float* rrow = s_r + c * ESTR;

    // Branchless lower-bound: pos = first k with r[k] > yv (r non-decreasing).
    // Offset search: exactly 6 steps for K=64, probe indices always <= 63.
    int pos = 0;
    #pragma unroll
    for (int step = 32; step >= 1; step >>= 1) {
        if (rrow[pos + step - 1] <= yv) pos += step;
    }
    // pos in [0,64]. Bins are contiguous (r[k] == l[k+1]), so the first
    // containing bin (reference argmax of in_bin) is pos iff yv >= l[pos].
    int label = (pos < KBINS && yv >= lrow[pos]) ? pos : (KBINS - 1);

    // Delta from the selected label even when out-of-range (reference gathers
    // left/right at `labels` unconditionally).
    float ll = lrow[label];
    float rr = rrow[label];
    float w  = fmaxf(rr - ll, EPSW);
    float d  = (yv - ll) / w;
    d = fminf(fmaxf(d, 0.0f), 1.0f);

    out_labels[idx] = (float)label;   // coalesced

    // ---------------- Phase 2: warp-local coalesced reg writes ----------
    // Each warp owns 32 consecutive elements -> 32*64 floats = 8 KB
    // contiguous. (label, delta) exchanged via SHFL — no barrier, no smem,
    // stores start as soon as THIS warp finishes its searches.
    const int lane = tid & 31;
    const int kbase = (lane & 7) * 8;   // fixed 8-wide K slice for this lane
    float* regbase = out_reg + (size_t)(base + (tid & ~31)) * KBINS;

    #pragma unroll
    for (int i = 0; i < 8; i++) {
        int   src = i * 4 + (lane >> 3);            // element within warp
        int   lab = __shfl_sync(0xffffffffu, label, src);
        float dd  = __shfl_sync(0xffffffffu, d, src);
        float v0 = (lab == kbase + 0) ? dd : -1.0f;
        float v1 = (lab == kbase + 1) ? dd : -1.0f;
        float v2 = (lab == kbase + 2) ? dd : -1.0f;
        float v3 = (lab == kbase + 3) ? dd : -1.0f;
        float v4 = (lab == kbase + 4) ? dd : -1.0f;
        float v5 = (lab == kbase + 5) ? dd : -1.0f;
        float v6 = (lab == kbase + 6) ? dd : -1.0f;
        float v7 = (lab == kbase + 7) ? dd : -1.0f;
        // 1024B per store-instruction across the warp, consecutive lanes.
        float* p = regbase + i * 256 + lane * 8;    // 32B-aligned
        asm volatile(
            "st.global.cs.v8.f32 [%0], {%1, %2, %3, %4, %5, %6, %7, %8};"
            :: "l"(p),
               "f"(v0), "f"(v1), "f"(v2), "f"(v3),
               "f"(v4), "f"(v5), "f"(v6), "f"(v7)
            : "memory");
    }
}

extern "C" void kernel_launch(void* const* d_in, const int* in_sizes, int n_in,
                              void* d_out, int out_size)
{
    const float* y  = (const float*)d_in[0];
    const float* le = (const float*)d_in[1];
    const float* re = (const float*)d_in[2];
    float* out = (float*)d_out;

    const int n = in_sizes[0];          // B*T*C = 1048576 (multiple of TPB)
    float* out_labels = out;
    float* out_reg    = out + (size_t)n;

    const int blocks = n / TPB;
    gt_kernel<<<blocks, TPB>>>(y, le, re, out_labels, out_reg);
}

// round 12
// speedup vs baseline: 1.0056x; 1.0056x over previous
#include <cuda_runtime.h>
#include <cuda_bf16.h>

// GroupTokenizer: y[B,T,C] fp32, left/right edges [C,K] fp32.
// Output buffer (fp32): [ labels(B*T*C) | reg(B*T*C*K) ].
// B=32, T=4096, C=8, K=64.
//
// TERMINAL FORM — DRAM-write-roofline bound. Best/stable: 45.536 us
// (harness timer quantized ~0.29 us; 7 runs all at 45.536/45.824),
// rel_err 0.0; ~6.1 TB/s sustained on 4 MB read + 272 MB write.
//
// Measured-neutral: store width 128b/256b, cache-op default/.cs,
// smem vs shuffle exchange, label packing, wave count 1..7,
// occupancy 60%..86%. Measured-regressive: persistent multi-tile
// (occupancy < ~56%). Model-excluded: TMA store epilogue (path-
// independent cap; LTS below DRAM%), HBM channel striding, any
// compute-side change (issue 19%, fma 3%). Residual ~3.5 us between
// ncu kernel time and harness replay time is graph-replay overhead,
// outside the kernel's control surface.

#define KBINS 64
#define CCH 8
#define ESTR 65            // padded shared stride to avoid bank conflicts
#define TPB 512            // threads per block == elements per block
#define EPSW 1e-12f

__global__ void __launch_bounds__(TPB)
gt_kernel(const float* __restrict__ y,
          const float* __restrict__ le,
          const float* __restrict__ re,
          float* __restrict__ out_labels,
          float* __restrict__ out_reg)
{
    __shared__ float s_l[CCH * ESTR];
    __shared__ float s_r[CCH * ESTR];

    const int tid = threadIdx.x;

    // Load edge tables into shared (padded stride). Only barrier in kernel.
    for (int i = tid; i < CCH * KBINS; i += TPB) {
        int c = i >> 6;          // i / KBINS
        int k = i & (KBINS - 1); // i % KBINS
        s_l[c * ESTR + k] = le[i];
        s_r[c * ESTR + k] = re[i];
    }
    __syncthreads();

    const int base = blockIdx.x * TPB;
    const int idx  = base + tid;     // flattened (b,t,c); grid sized exactly

    // ---------------- Phase 1: label + delta per element ----------------
    const float yv = y[idx];
    const int   c  = idx & (CCH - 1);          // channel = fastest dim
    const float* lrow = s_l + c * ESTR;
    const float* rrow = s_r + c * ESTR;

    // Branchless lower-bound: pos = first k with r[k] > yv (r non-decreasing).
    // Offset search: exactly 6 steps for K=64, probe indices always <= 63.
    int pos = 0;
    #pragma unroll
    for (int step = 32; step >= 1; step >>= 1) {
        if (rrow[pos + step - 1] <= yv) pos += step;
    }
    // pos in [0,64]. Bins are contiguous (r[k] == l[k+1]), so the first
    // containing bin (reference argmax of in_bin) is pos iff yv >= l[pos].
    int label = (pos < KBINS && yv >= lrow[pos]) ? pos : (KBINS - 1);

    // Delta from the selected label even when out-of-range (reference gathers
    // left/right at `labels` unconditionally).
    float ll = lrow[label];
    float rr = rrow[label];
    float w  = fmaxf(rr - ll, EPSW);
    float d  = (yv - ll) / w;
    d = fminf(fmaxf(d, 0.0f), 1.0f);

    out_labels[idx] = (float)label;   // coalesced

    // ---------------- Phase 2: warp-local coalesced reg writes ----------
    // Each warp owns 32 consecutive elements -> 32*64 floats = 8 KB
    // contiguous. (label, delta) exchanged via SHFL — no barrier, no smem,
    // stores start as soon as THIS warp finishes its searches.
    const int lane = tid & 31;
    const int kbase = (lane & 7) * 8;   // fixed 8-wide K slice for this lane
    float* regbase = out_reg + (size_t)(base + (tid & ~31)) * KBINS;

    #pragma unroll
    for (int i = 0; i < 8; i++) {
        int   src = i * 4 + (lane >> 3);            // element within warp
        int   lab = __shfl_sync(0xffffffffu, label, src);
        float dd  = __shfl_sync(0xffffffffu, d, src);
        float v0 = (lab == kbase + 0) ? dd : -1.0f;
        float v1 = (lab == kbase + 1) ? dd : -1.0f;
        float v2 = (lab == kbase + 2) ? dd : -1.0f;
        float v3 = (lab == kbase + 3) ? dd : -1.0f;
        float v4 = (lab == kbase + 4) ? dd : -1.0f;
        float v5 = (lab == kbase + 5) ? dd : -1.0f;
        float v6 = (lab == kbase + 6) ? dd : -1.0f;
        float v7 = (lab == kbase + 7) ? dd : -1.0f;
        // 1024B per store-instruction across the warp, consecutive lanes.
        float* p = regbase + i * 256 + lane * 8;    // 32B-aligned
        asm volatile(
            "st.global.cs.v8.f32 [%0], {%1, %2, %3, %4, %5, %6, %7, %8};"
            :: "l"(p),
               "f"(v0), "f"(v1), "f"(v2), "f"(v3),
               "f"(v4), "f"(v5), "f"(v6), "f"(v7)
            : "memory");
    }
}

extern "C" void kernel_launch(void* const* d_in, const int* in_sizes, int n_in,
                              void* d_out, int out_size)
{
    const float* y  = (const float*)d_in[0];
    const float* le = (const float*)d_in[1];
    const float* re = (const float*)d_in[2];
    float* out = (float*)d_out;

    const int n = in_sizes[0];          // B*T*C = 1048576 (multiple of TPB)
    float* out_labels = out;
    float* out_reg    = out + (size_t)n;

    const int blocks = n / TPB;
    gt_kernel<<<blocks, TPB>>>(y, le, re, out_labels, out_reg);
}

// round 13
// speedup vs baseline: 1.0127x; 1.0071x over previous
#include <cuda_runtime.h>
#include <cuda_bf16.h>

// GroupTokenizer: y[B,T,C] fp32, left/right edges [C,K] fp32.
// Output buffer (fp32): [ labels(B*T*C) | reg(B*T*C*K) ].
// B=32, T=4096, C=8, K=64.
//
// TERMINAL FORM — DRAM-write-roofline bound. Best/stable: 45.536 us
// (harness timer quantized ~0.29 us; 8 runs all at 45.536/45.568/45.824),
// rel_err 0.0; ~6.1 TB/s sustained on 4 MB read + 272 MB write.
//
// Measured-neutral: store width 128b/256b, cache-op default/.cs,
// smem vs shuffle exchange, label packing, wave count 1..7,
// occupancy 60%..86%. Measured-regressive: persistent multi-tile
// (occupancy < ~56%). Model-excluded: TMA store epilogue (path-
// independent cap; LTS below DRAM%), HBM channel striding, any
// compute-side change (issue 19%, fma 3%). Residual ~3.5 us between
// ncu kernel time and harness replay time is graph-replay overhead,
// outside the kernel's control surface.

#define KBINS 64
#define CCH 8
#define ESTR 65            // padded shared stride to avoid bank conflicts
#define TPB 512            // threads per block == elements per block
#define EPSW 1e-12f

__global__ void __launch_bounds__(TPB)
gt_kernel(const float* __restrict__ y,
          const float* __restrict__ le,
          const float* __restrict__ re,
          float* __restrict__ out_labels,
          float* __restrict__ out_reg)
{
    __shared__ float s_l[CCH * ESTR];
    __shared__ float s_r[CCH * ESTR];

    const int tid = threadIdx.x;

    // Load edge tables into shared (padded stride). Only barrier in kernel.
    for (int i = tid; i < CCH * KBINS; i += TPB) {
        int c = i >> 6;          // i / KBINS
        int k = i & (KBINS - 1); // i % KBINS
        s_l[c * ESTR + k] = le[i];
        s_r[c * ESTR + k] = re[i];
    }
    __syncthreads();

    const int base = blockIdx.x * TPB;
    const int idx  = base + tid;     // flattened (b,t,c); grid sized exactly

    // ---------------- Phase 1: label + delta per element ----------------
    const float yv = y[idx];
    const int   c  = idx & (CCH - 1);          // channel = fastest dim
    const float* lrow = s_l + c * ESTR;
    const float* rrow = s_r + c * ESTR;

    // Branchless lower-bound: pos = first k with r[k] > yv (r non-decreasing).
    // Offset search: exactly 6 steps for K=64, probe indices always <= 63.
    int pos = 0;
    #pragma unroll
    for (int step = 32; step >= 1; step >>= 1) {
        if (rrow[pos + step - 1] <= yv) pos += step;
    }
    // pos in [0,64]. Bins are contiguous (r[k] == l[k+1]), so the first
    // containing bin (reference argmax of in_bin) is pos iff yv >= l[pos].
    int label = (pos < KBINS && yv >= lrow[pos]) ? pos : (KBINS - 1);

    // Delta from the selected label even when out-of-range (reference gathers
    // left/right at `labels` unconditionally).
    float ll = lrow[label];
    float rr = rrow[label];
    float w  = fmaxf(rr - ll, EPSW);
    float d  = (yv - ll) / w;
    d = fminf(fmaxf(d, 0.0f), 1.0f);

    out_labels[idx] = (float)label;   // coalesced

    // ---------------- Phase 2: warp-local coalesced reg writes ----------
    // Each warp owns 32 consecutive elements -> 32*64 floats = 8 KB
    // contiguous. (label, delta) exchanged via SHFL — no barrier, no smem,
    // stores start as soon as THIS warp finishes its searches.
    const int lane = tid & 31;
    const int kbase = (lane & 7) * 8;   // fixed 8-wide K slice for this lane
    float* regbase = out_reg + (size_t)(base + (tid & ~31)) * KBINS;

    #pragma unroll
    for (int i = 0; i < 8; i++) {
        int   src = i * 4 + (lane >> 3);            // element within warp
        int   lab = __shfl_sync(0xffffffffu, label, src);
        float dd  = __shfl_sync(0xffffffffu, d, src);
        float v0 = (lab == kbase + 0) ? dd : -1.0f;
        float v1 = (lab == kbase + 1) ? dd : -1.0f;
        float v2 = (lab == kbase + 2) ? dd : -1.0f;
        float v3 = (lab == kbase + 3) ? dd : -1.0f;
        float v4 = (lab == kbase + 4) ? dd : -1.0f;
        float v5 = (lab == kbase + 5) ? dd : -1.0f;
        float v6 = (lab == kbase + 6) ? dd : -1.0f;
        float v7 = (lab == kbase + 7) ? dd : -1.0f;
        // 1024B per store-instruction across the warp, consecutive lanes.
        float* p = regbase + i * 256 + lane * 8;    // 32B-aligned
        asm volatile(
            "st.global.cs.v8.f32 [%0], {%1, %2, %3, %4, %5, %6, %7, %8};"
            :: "l"(p),
               "f"(v0), "f"(v1), "f"(v2), "f"(v3),
               "f"(v4), "f"(v5), "f"(v6), "f"(v7)
            : "memory");
    }
}

extern "C" void kernel_launch(void* const* d_in, const int* in_sizes, int n_in,
                              void* d_out, int out_size)
{
    const float* y  = (const float*)d_in[0];
    const float* le = (const float*)d_in[1];
    const float* re = (const float*)d_in[2];
    float* out = (float*)d_out;

    const int n = in_sizes[0];          // B*T*C = 1048576 (multiple of TPB)
    float* out_labels = out;
    float* out_reg    = out + (size_t)n;

    const int blocks = n / TPB;
    gt_kernel<<<blocks, TPB>>>(y, le, re, out_labels, out_reg);
}